// round 9
// baseline (speedup 1.0000x reference)
#include <cuda_runtime.h>
#include <math.h>

// Problem dims
#define BATCH 32
#define CCH   192
#define HW    4096                 // 64*64
#define NTOT  (BATCH * CCH * HW)   // 25,165,824 elements
#define N4    (NTOT / 4)           // float4 count (6,291,456)
#define LOG2E 1.4426950408889634f

__device__ __forceinline__ float softplus_fast(float x) {
    return fmaxf(x, 0.0f) + __logf(1.0f + __expf(-fabsf(x)));
}
__device__ __forceinline__ float sigmoid_acc(float x) {
    return fmaf(0.5f, tanhf(0.5f * x), 0.5f);
}
__device__ __forceinline__ float ex2_approx(float x) {
    float r; asm("ex2.approx.f32 %0, %1;" : "=f"(r) : "f"(x)); return r;
}
__device__ __forceinline__ float rcp_approx(float x) {
    float r; asm("rcp.approx.f32 %0, %1;" : "=f"(r) : "f"(x)); return r;
}

// Shared layout per warp (48 floats):
// [0:3)=sp0 [3:12)=W1 [12:21)=W2 [21:24)=w3
// [24:27)=b0 [27:30)=b1 [30:33)=b2 [33]=b3 [34:43)=RAW f0..f2
// (factors stored raw; tanh applied only on the cold fallback path)

// Generic full-MLP CDF (fallback; factors raw in S[34..42])
__device__ float cdf_full_raw(const float* __restrict__ S, float x) {
    float v[3], w[3];
    #pragma unroll
    for (int o = 0; o < 3; o++) {
        v[o] = fmaf(S[0 + o], x, S[24 + o]);
        v[o] = fmaf(tanhf(S[34 + o]), tanhf(v[o]), v[o]);
    }
    #pragma unroll
    for (int o = 0; o < 3; o++) {
        w[o] = S[27 + o] + S[3 + o*3 + 0]*v[0] + S[3 + o*3 + 1]*v[1] + S[3 + o*3 + 2]*v[2];
        w[o] = fmaf(tanhf(S[37 + o]), tanhf(w[o]), w[o]);
    }
    #pragma unroll
    for (int o = 0; o < 3; o++) {
        v[o] = S[30 + o] + S[12 + o*3 + 0]*w[0] + S[12 + o*3 + 1]*w[1] + S[12 + o*3 + 2]*w[2];
        v[o] = fmaf(tanhf(S[40 + o]), tanhf(v[o]), v[o]);
    }
    float s = S[33] + S[21]*v[0] + S[22]*v[1] + S[23]*v[2];
    return sigmoid_acc(s);
}

__device__ __noinline__ void fp_fallback(const float* __restrict__ S, const float4 zz,
                                         float4* zh_out, float4* lk_out) {
    float in[4] = {zz.x, zz.y, zz.z, zz.w};
    float oh[4], ol[4];
    #pragma unroll
    for (int i = 0; i < 4; i++) {
        float h  = rintf(in[i]);
        float up = cdf_full_raw(S, h + 0.5f);
        float lo = cdf_full_raw(S, h - 0.5f);
        oh[i] = h;
        ol[i] = fmaxf(up - lo, 1e-9f);
    }
    *zh_out = make_float4(oh[0], oh[1], oh[2], oh[3]);
    *lk_out = make_float4(ol[0], ol[1], ol[2], ol[3]);
}

// ---------------------------------------------------------------------------
// Single fused kernel. One block per (b,c) slice; 16 elements/thread
// (4 front-batched float4 loads, MLP_p1 = 4). Channel uniform per block.
//
// Warp-autonomous preamble (NO block barriers): each warp loads + softplus's
// the 43 channel params into its private shared slab, __syncwarp, then every
// lane redundantly composes the affine collapse logit(x) = a*x + d. The whole
// preamble critical path (~550 cy with L2-hot params) hides under the ~600 cy
// DRAM latency of the already-issued z loads.
//
// Hot path per element:
//   h   = rint(z)                               (half-to-even == jnp.round)
//   e1  = 2^(na*h + nd)   == exp(-(a*(h+0.5)+d))
//   e2  = e1 * ea         == exp(-(logit - a))
//   lik = max((e2-e1) * rcp((1+e1)*(1+e2)), 1e-9)
// Tails: e1->inf => NaN => fmax -> 1e-9 (== clipped ref); e1->0 => 0 -> 1e-9.
// ---------------------------------------------------------------------------
__global__ void __launch_bounds__(256)
fp_main(const float* __restrict__ z, float* __restrict__ out,
        const float* __restrict__ m0, const float* __restrict__ m1,
        const float* __restrict__ m2, const float* __restrict__ m3,
        const float* __restrict__ b0, const float* __restrict__ b1,
        const float* __restrict__ b2, const float* __restrict__ b3,
        const float* __restrict__ f0, const float* __restrict__ f1,
        const float* __restrict__ f2) {
    __shared__ float S8[8][48];

    const int tid  = threadIdx.x;
    const int warp = tid >> 5;
    const int lane = tid & 31;
    const int c  = blockIdx.x % CCH;                // one block per (b,c) slice
    const int n4 = blockIdx.x * 1024 + tid;         // first float4 index

    const float4* zin = reinterpret_cast<const float4*>(z);
    float4* o = reinterpret_cast<float4*>(out);

    // Front-batch 4 independent streaming loads (MLP_p1 = 4); preamble hides
    // under their DRAM latency.
    float4 zz0 = __ldcs(zin + n4);
    float4 zz1 = __ldcs(zin + n4 + 256);
    float4 zz2 = __ldcs(zin + n4 + 512);
    float4 zz3 = __ldcs(zin + n4 + 768);

    float* S = S8[warp];

    // ---- lane-parallel param load/processing into warp-private shared ----
    {
        float v;
        if (lane < 3)       v = softplus_fast(m0[c * 3 + lane]);
        else if (lane < 12) v = softplus_fast(m1[c * 9 + (lane - 3)]);
        else if (lane < 21) v = softplus_fast(m2[c * 9 + (lane - 12)]);
        else if (lane < 24) v = softplus_fast(m3[c * 3 + (lane - 21)]);
        else if (lane < 27) v = b0[c * 3 + (lane - 24)];
        else if (lane < 30) v = b1[c * 3 + (lane - 27)];
        else                v = b2[c * 3 + (lane - 30)];   // lanes 30,31 -> b2[0..1]
        S[lane] = v;

        float v2 = 0.0f;
        if (lane == 0)      v2 = b2[c * 3 + 2];
        else if (lane == 1) v2 = b3[c];
        else if (lane < 11) {                              // lanes 2..10 -> f values
            int k = lane - 2;                              // 0..8
            const float* fp = (k < 3) ? f0 : ((k < 6) ? f1 : f2);
            v2 = fp[c * 3 + (k % 3)];
        }
        if (lane < 11) S[32 + lane] = v2;                  // slots 32..42

        // affine iff ALL raw factors are exactly zero (tanh(0)==0)
        unsigned nz = __ballot_sync(0xffffffffu, (lane >= 2 && lane < 11) && (v2 != 0.0f));
        __syncwarp();

        if (nz == 0) {
            // ---- every lane redundantly composes the affine collapse ----
            float v1a[3], u1a[3], v2a[3], u2a[3];
            #pragma unroll
            for (int oo = 0; oo < 3; oo++) {
                v1a[oo] = S[3+oo*3+0]*S[0]  + S[3+oo*3+1]*S[1]  + S[3+oo*3+2]*S[2];
                u1a[oo] = S[3+oo*3+0]*S[24] + S[3+oo*3+1]*S[25] + S[3+oo*3+2]*S[26] + S[27+oo];
            }
            #pragma unroll
            for (int oo = 0; oo < 3; oo++) {
                v2a[oo] = S[12+oo*3+0]*v1a[0] + S[12+oo*3+1]*v1a[1] + S[12+oo*3+2]*v1a[2];
                u2a[oo] = S[12+oo*3+0]*u1a[0] + S[12+oo*3+1]*u1a[1] + S[12+oo*3+2]*u1a[2] + S[30+oo];
            }
            float a = S[21]*v2a[0] + S[22]*v2a[1] + S[23]*v2a[2];
            float d = S[21]*u2a[0] + S[22]*u2a[1] + S[23]*u2a[2] + S[33];

            const float na = -a * LOG2E;
            const float nd = -(0.5f * a + d) * LOG2E;
            const float ea = __expf(a);

            float in[16] = {zz0.x, zz0.y, zz0.z, zz0.w, zz1.x, zz1.y, zz1.z, zz1.w,
                            zz2.x, zz2.y, zz2.z, zz2.w, zz3.x, zz3.y, zz3.z, zz3.w};
            float oh[16], ol[16];
            #pragma unroll
            for (int i = 0; i < 16; i++) {
                float h   = rintf(in[i]);
                float e1  = ex2_approx(fmaf(na, h, nd));
                float e2  = e1 * ea;
                float num = e2 - e1;
                float den = (1.0f + e1) * (1.0f + e2);
                oh[i] = h;
                ol[i] = fmaxf(num * rcp_approx(den), 1e-9f);
            }
            o[n4]            = make_float4(oh[0],  oh[1],  oh[2],  oh[3]);
            o[n4 + 256]      = make_float4(oh[4],  oh[5],  oh[6],  oh[7]);
            o[n4 + 512]      = make_float4(oh[8],  oh[9],  oh[10], oh[11]);
            o[n4 + 768]      = make_float4(oh[12], oh[13], oh[14], oh[15]);
            o[n4 + N4]       = make_float4(ol[0],  ol[1],  ol[2],  ol[3]);
            o[n4 + N4 + 256] = make_float4(ol[4],  ol[5],  ol[6],  ol[7]);
            o[n4 + N4 + 512] = make_float4(ol[8],  ol[9],  ol[10], ol[11]);
            o[n4 + N4 + 768] = make_float4(ol[12], ol[13], ol[14], ol[15]);
        } else {
            float4 zh, lk;
            fp_fallback(S, zz0, &zh, &lk);
            o[n4] = zh;            o[n4 + N4] = lk;
            fp_fallback(S, zz1, &zh, &lk);
            o[n4 + 256] = zh;      o[n4 + N4 + 256] = lk;
            fp_fallback(S, zz2, &zh, &lk);
            o[n4 + 512] = zh;      o[n4 + N4 + 512] = lk;
            fp_fallback(S, zz3, &zh, &lk);
            o[n4 + 768] = zh;      o[n4 + N4 + 768] = lk;
        }
    }
}

extern "C" void kernel_launch(void* const* d_in, const int* in_sizes, int n_in,
                              void* d_out, int out_size) {
    const float* z  = (const float*)d_in[0];
    const float* m0 = (const float*)d_in[1];
    const float* m1 = (const float*)d_in[2];
    const float* m2 = (const float*)d_in[3];
    const float* m3 = (const float*)d_in[4];
    const float* b0 = (const float*)d_in[5];
    const float* b1 = (const float*)d_in[6];
    const float* b2 = (const float*)d_in[7];
    const float* b3 = (const float*)d_in[8];
    const float* f0 = (const float*)d_in[9];
    const float* f1 = (const float*)d_in[10];
    const float* f2 = (const float*)d_in[11];

    const int nblocks = N4 / 1024;  // 6144 = one block per (b,c) slice
    fp_main<<<nblocks, 256>>>(z, (float*)d_out,
                              m0, m1, m2, m3, b0, b1, b2, b3, f0, f1, f2);
}